// round 7
// baseline (speedup 1.0000x reference)
#include <cuda_runtime.h>

#define DH 64
#define MAX_BH 128
#define MAX_N 8192
#define NSPLIT 8

// ---- scratch (static __device__: no allocation) ----
__device__ float g_ctxp[NSPLIT * MAX_BH * DH * DH];  // per-split ctx partials
__device__ float g_vsump[NSPLIT * MAX_BH * DH];      // per-split vsum partials
__device__ float g_rinv[MAX_BH * MAX_N];             // per-row 1/denom (from V)

typedef unsigned long long u64t;

__device__ __forceinline__ u64t pk2(float lo, float hi) {
    u64t r; asm("mov.b64 %0, {%1, %2};" : "=l"(r) : "f"(lo), "f"(hi)); return r;
}
__device__ __forceinline__ void upk2(u64t v, float& lo, float& hi) {
    asm("mov.b64 {%0, %1}, %2;" : "=f"(lo), "=f"(hi) : "l"(v));
}
__device__ __forceinline__ void fma2(u64t& acc, u64t a, u64t b) {
    asm("fma.rn.f32x2 %0, %1, %2, %0;" : "+l"(acc) : "l"(a), "l"(b));
}
__device__ __forceinline__ float elu1(float v) { return v > 0.f ? v + 1.f : __expf(v); }

__device__ __forceinline__ unsigned smem_u32(const void* p) {
    return (unsigned)__cvta_generic_to_shared(p);
}
__device__ __forceinline__ void cp16(unsigned s, const float* g) {
    asm volatile("cp.async.cg.shared.global [%0], [%1], 16;" :: "r"(s), "l"(g));
}
#define CP_COMMIT() asm volatile("cp.async.commit_group;" ::: "memory")
#define CP_WAIT(n)  asm volatile("cp.async.wait_group %0;" :: "n"(n) : "memory")

// ===========================================================================
// K1: ctx[d][e] = sum_n v2[n,d]*x[n,e], vsum[d] = sum_n v2[n,d]; stash rinv.
// Round-4 (measured-fastest) two-barrier pipeline; GEMM remapped to 4d x 8e
// per thread with TWO accumulator copies (warps 0-3 rows 0-15, warps 4-7 rows
// 16-31) so acc regs fit 3 CTAs/SM (24 warps) under launch_bounds(256,3).
// ===========================================================================
#define K1_STV   0            // 2*32*68 = 4352
#define K1_STK   4352         // 4352
#define K1_STM   8704         // 64
#define K1_V2D   8768         // 32*160 = 5120 (dup v2)
#define K1_XS    13888        // 32*96 = 3072 (raw x)
#define K1_FLOATS 16960       // 67840 bytes -> 3 CTAs/SM

__global__ void __launch_bounds__(256, 3)
ctx_kernel(const float* __restrict__ Kg, const float* __restrict__ Vg,
           const float* __restrict__ mask, const float* __restrict__ c,
           int csize, int N)
{
    extern __shared__ float sm[];
    float* stV = sm + K1_STV;
    float* stK = sm + K1_STK;
    float* stM = sm + K1_STM;
    float* v2d = sm + K1_V2D;
    float* x_s = sm + K1_XS;

    const int split = blockIdx.x, bh = blockIdx.y;
    const int rows  = N / gridDim.x;
    const int n0    = split * rows;
    const float k   = (csize > 1) ? c[bh % csize] : c[0];

    const int tid   = threadIdx.x;
    const int lrow  = tid >> 3;
    const int lcol8 = tid & 7;
    const int wid   = tid >> 5, lane = tid & 31;
    const int copyid = wid >> 2;              // 0: rows 0-15, 1: rows 16-31
    const int cwid   = wid & 3;
    const int dgrp16 = cwid * 4 + (lane >> 3); // 0..15 (4 d's each)
    const int egrp   = lane & 7;
    const int aoff   = (dgrp16 >> 1) * 20 + (dgrp16 & 1) * 8;  // dup-pair offset

    const float* Kp = Kg + (size_t)bh * N * DH;
    const float* Vp = Vg + (size_t)bh * N * DH;

    const int pr_r0  = tid >> 4;
    const int pr_off = (tid & 15) * 4;

    auto prefetch = [&](int t0, int p) {
        const float* gv = Vp + (size_t)(n0 + t0) * DH;
        const float* gk = Kp + (size_t)(n0 + t0) * DH;
        const unsigned sv = smem_u32(stV + p * 2176);
        const unsigned sk = smem_u32(stK + p * 2176);
        cp16(sv + (pr_r0 * 68 + pr_off) * 4,        gv + pr_r0 * DH + pr_off);
        cp16(sv + ((pr_r0 + 16) * 68 + pr_off) * 4, gv + (pr_r0 + 16) * DH + pr_off);
        cp16(sk + (pr_r0 * 68 + pr_off) * 4,        gk + pr_r0 * DH + pr_off);
        cp16(sk + ((pr_r0 + 16) * 68 + pr_off) * 4, gk + (pr_r0 + 16) * DH + pr_off);
        if (tid < 8) cp16(smem_u32(stM + p * 32) + tid * 16, mask + n0 + t0 + tid * 4);
    };

    u64t acc[4][4] = {};
    float vsum[8] = {0.f,0.f,0.f,0.f,0.f,0.f,0.f,0.f};

    const int T = rows / 32;
    prefetch(0, 0);
    CP_COMMIT();

    for (int t = 0; t < T; t++) {
        const int p = t & 1;
        if (t + 1 < T) { prefetch((t + 1) * 32, p ^ 1); CP_COMMIT(); CP_WAIT(1); }
        else           { CP_WAIT(0); }
        __syncthreads();   // stage[p] visible; prior GEMM done with v2d/x_s

        // ---- elementwise from stage ----
        const int n = n0 + t * 32 + lrow;
        const float* vr = stV + p * 2176 + lrow * 68 + lcol8 * 8;
        const float4 va = *(const float4*)vr;
        const float4 vb = *(const float4*)(vr + 4);
        float ss = va.x*va.x + va.y*va.y + va.z*va.z + va.w*va.w
                 + vb.x*vb.x + vb.y*vb.y + vb.z*vb.z + vb.w*vb.w;
        ss += __shfl_xor_sync(0xffffffffu, ss, 1);
        ss += __shfl_xor_sync(0xffffffffu, ss, 2);
        ss += __shfl_xor_sync(0xffffffffu, ss, 4);
        const float denom = fmaxf(fmaf(k, ss, 1.f), 1e-15f);
        const float rinv  = 1.f / denom;
        const float g     = 2.f * rinv;
        const float gm1   = g - 1.f;
        const float sgn   = (gm1 >= 0.f) ? 1.f : -1.f;
        const float d2    = sgn * fmaxf(fabsf(gm1), 1e-10f);
        const float m     = stM[p * 32 + lrow];
        const float xs    = g / d2 * m;
        const float d2m   = d2 * m;

        float* xw = &x_s[lrow * 96 + lcol8 * 12];
        *(float4*)(xw)     = make_float4(va.x*xs, va.y*xs, va.z*xs, va.w*xs);
        *(float4*)(xw + 4) = make_float4(vb.x*xs, vb.y*xs, vb.z*xs, vb.w*xs);

        const float* kr = stK + p * 2176 + lrow * 68 + lcol8 * 8;
        const float4 ka = *(const float4*)kr;
        const float4 kb = *(const float4*)(kr + 4);
        float w[8];
        w[0] = d2m*elu1(ka.x*rinv); w[1] = d2m*elu1(ka.y*rinv);
        w[2] = d2m*elu1(ka.z*rinv); w[3] = d2m*elu1(ka.w*rinv);
        w[4] = d2m*elu1(kb.x*rinv); w[5] = d2m*elu1(kb.y*rinv);
        w[6] = d2m*elu1(kb.z*rinv); w[7] = d2m*elu1(kb.w*rinv);
        float* vw = &v2d[lrow * 160 + lcol8 * 20];
        *(float4*)(vw)      = make_float4(w[0], w[0], w[1], w[1]);
        *(float4*)(vw + 4)  = make_float4(w[2], w[2], w[3], w[3]);
        *(float4*)(vw + 8)  = make_float4(w[4], w[4], w[5], w[5]);
        *(float4*)(vw + 12) = make_float4(w[6], w[6], w[7], w[7]);
        #pragma unroll
        for (int j = 0; j < 8; j++) vsum[j] += w[j];

        if (lcol8 == 0) g_rinv[(size_t)bh * N + n] = rinv;
        __syncthreads();

        // ---- GEMM: 16 rank-1 updates per copy, 4d x 8e per thread ----
        const int rbase = copyid * 16;
        #pragma unroll
        for (int rr = 0; rr < 16; rr++) {
            const int tt = rbase + rr;
            const ulonglong2 aA = *(const ulonglong2*)&v2d[tt * 160 + aoff];
            const ulonglong2 aB = *(const ulonglong2*)&v2d[tt * 160 + aoff + 4];
            const ulonglong2* bp = (const ulonglong2*)&x_s[tt * 96 + egrp * 12];
            const ulonglong2 b03 = bp[0], b47 = bp[1];
            const u64t A[4] = {aA.x, aA.y, aB.x, aB.y};
            const u64t B[4] = {b03.x, b03.y, b47.x, b47.y};
            #pragma unroll
            for (int dd = 0; dd < 4; dd++) {
                fma2(acc[dd][0], A[dd], B[0]);
                fma2(acc[dd][1], A[dd], B[1]);
                fma2(acc[dd][2], A[dd], B[2]);
                fma2(acc[dd][3], A[dd], B[3]);
            }
        }
    }
    __syncthreads();

    // ---- reduce the 2 copies via smem, write split partial ----
    float* red = v2d;   // 4096 floats needed; v2d has 5120
    #pragma unroll
    for (int p = 0; p < 2; p++) {
        if (copyid == p) {
            #pragma unroll
            for (int dd = 0; dd < 4; dd++) {
                #pragma unroll
                for (int ee = 0; ee < 4; ee++) {
                    float f0, f1; upk2(acc[dd][ee], f0, f1);
                    const int idx = (dgrp16 * 4 + dd) * 64 + egrp * 8 + ee * 2;
                    if (p == 0) { red[idx] = f0; red[idx + 1] = f1; }
                    else        { red[idx] += f0; red[idx + 1] += f1; }
                }
            }
        }
        __syncthreads();
    }
    float* dst = g_ctxp + ((size_t)bh * NSPLIT + split) * (DH * DH);
    for (int i = tid; i < DH * DH; i += 256) dst[i] = red[i];

    // ---- vsum partial ----
    float* vb2 = x_s;
    #pragma unroll
    for (int j = 0; j < 8; j++) vb2[lrow * 64 + lcol8 * 8 + j] = vsum[j];
    __syncthreads();
    if (tid < DH) {
        float s = 0.f;
        #pragma unroll
        for (int r = 0; r < 32; r++) s += vb2[r * 64 + tid];
        g_vsump[((size_t)bh * NSPLIT + split) * DH + tid] = s;
    }
}

// ===========================================================================
// K2: fused split-reduce prologue + per-row X = (v1@ctx)/(v1.vsum) + geometry.
// 128-row tiles, 4n x 8e thread tiles. ctx plain stride 64 (b-loads dedup
// across rgrp; worst 2 phases), v1 raw stride 66 (a-load banks {0,8,16,24}).
// Smem 50.9KB + launch_bounds(256,4) -> 4 CTAs/SM, 32 warps.
// ===========================================================================
#define V1S 66
#define K2_CTX  0                 // 64*64 = 4096
#define K2_V1   4096              // 128*66 = 8448
#define K2_DP   12544             // 128
#define K2_VS   12672             // 64
#define K2_FLOATS 12736           // 50944 bytes

__global__ void __launch_bounds__(256, 4)
out_kernel(const float* __restrict__ Qg, const float* __restrict__ c,
           int csize, int N, int splits, float* __restrict__ out)
{
    extern __shared__ float sm[];
    float* ctx_s = sm + K2_CTX;
    float* v1s   = sm + K2_V1;
    float* dpbuf = sm + K2_DP;
    float* vs_s  = sm + K2_VS;

    const int chunk = blockIdx.x, bh = blockIdx.y;
    const int rows  = N / gridDim.x;
    const int n0    = chunk * rows;
    const float k   = (csize > 1) ? c[bh % csize] : c[0];
    const float sk  = sqrtf(fabsf(k) + 1e-15f);
    const float maxnorm = (k < 0.f) ? (1.f - 0.004f) / sk : 1e15f;
    const bool  hyp = (k < 0.f);

    const int tid   = threadIdx.x;
    const int lrow  = tid >> 3, lcol8 = tid & 7;
    const int wid   = tid >> 5, lane = tid & 31;
    const int rgrp  = lane >> 3, egrp = lane & 7;
    const int e0    = egrp * 8;

    const float* Qp = Qg + (size_t)bh * N * DH;
    const float* rv = g_rinv + (size_t)bh * N;
    float*       Op = out + (size_t)bh * N * DH;

    // ---- fused reduce of K1 split partials (L2-hot) ----
    const float* bctx = g_ctxp + (size_t)bh * NSPLIT * DH * DH;
    for (int i = tid; i < DH * DH; i += 256) {
        float s = 0.f;
        for (int p = 0; p < splits; p++) s += bctx[p * DH * DH + i];
        ctx_s[i] = s;
    }
    if (tid < DH) {
        float s = 0.f;
        for (int p = 0; p < splits; p++) s += g_vsump[((size_t)bh * NSPLIT + p) * DH + tid];
        vs_s[tid] = s;
    }
    __syncthreads();

    const int nIter = rows / 128;
    for (int it = 0; it < nIter; it++) {
        const int base = n0 + it * 128;

        // ---- elementwise: v1 = elu(Q*rinv)+1 (raw store), dp = v1.vsum ----
        #pragma unroll
        for (int s = 0; s < 4; s++) {
            const int lr = s * 32 + lrow;
            const int n  = base + lr;
            const float rinv = rv[n];
            const size_t nb = (size_t)n * DH + lcol8 * 8;
            const float4 qa = *(const float4*)(Qp + nb);
            const float4 qb = *(const float4*)(Qp + nb + 4);
            float v1v[8];
            v1v[0] = elu1(qa.x*rinv); v1v[1] = elu1(qa.y*rinv);
            v1v[2] = elu1(qa.z*rinv); v1v[3] = elu1(qa.w*rinv);
            v1v[4] = elu1(qb.x*rinv); v1v[5] = elu1(qb.y*rinv);
            v1v[6] = elu1(qb.z*rinv); v1v[7] = elu1(qb.w*rinv);

            const int vc = lcol8 * 8;
            float dp = v1v[0]*vs_s[vc+0] + v1v[1]*vs_s[vc+1]
                     + v1v[2]*vs_s[vc+2] + v1v[3]*vs_s[vc+3]
                     + v1v[4]*vs_s[vc+4] + v1v[5]*vs_s[vc+5]
                     + v1v[6]*vs_s[vc+6] + v1v[7]*vs_s[vc+7];
            dp += __shfl_xor_sync(0xffffffffu, dp, 1);
            dp += __shfl_xor_sync(0xffffffffu, dp, 2);
            dp += __shfl_xor_sync(0xffffffffu, dp, 4);

            float* vw = &v1s[lr * V1S + vc];
            *(float2*)(vw)     = make_float2(v1v[0], v1v[1]);
            *(float2*)(vw + 2) = make_float2(v1v[2], v1v[3]);
            *(float2*)(vw + 4) = make_float2(v1v[4], v1v[5]);
            *(float2*)(vw + 6) = make_float2(v1v[6], v1v[7]);
            if (lcol8 == 0) dpbuf[lr] = dp;
        }
        __syncthreads();

        // ---- GEMV: thread = 4 rows x 8 e ----
        const int row0 = wid * 16 + rgrp * 4;
        u64t acc[4][4] = {};
        #pragma unroll
        for (int d = 0; d < DH; d += 2) {
            const ulonglong2* bp0 = (const ulonglong2*)&ctx_s[d * 64 + e0];
            const ulonglong2* bp1 = (const ulonglong2*)&ctx_s[(d + 1) * 64 + e0];
            const ulonglong2 bA = bp0[0], bB = bp0[1];
            const ulonglong2 cA = bp1[0], cB = bp1[1];
            #pragma unroll
            for (int rr = 0; rr < 4; rr++) {
                const u64t ar = *(const u64t*)&v1s[(row0 + rr) * V1S + d];
                float a0, a1; upk2(ar, a0, a1);
                const u64t aa0 = pk2(a0, a0), aa1 = pk2(a1, a1);
                fma2(acc[rr][0], aa0, bA.x); fma2(acc[rr][1], aa0, bA.y);
                fma2(acc[rr][2], aa0, bB.x); fma2(acc[rr][3], aa0, bB.y);
                fma2(acc[rr][0], aa1, cA.x); fma2(acc[rr][1], aa1, cA.y);
                fma2(acc[rr][2], aa1, cB.x); fma2(acc[rr][3], aa1, cB.y);
            }
        }

        // ---- tail: Dinv scale, project -> mobius(0.5) -> project, store ----
        #pragma unroll
        for (int rr = 0; rr < 4; rr++) {
            const int lr = row0 + rr;
            const int n  = base + lr;
            float x[8];
            upk2(acc[rr][0], x[0], x[1]); upk2(acc[rr][1], x[2], x[3]);
            upk2(acc[rr][2], x[4], x[5]); upk2(acc[rr][3], x[6], x[7]);

            const float dp = dpbuf[lr];
            const float Dinv = 1.f / ((dp == 0.f) ? 1e-5f : dp);
            float n2 = 0.f;
            #pragma unroll
            for (int j = 0; j < 8; j++) { x[j] *= Dinv; n2 += x[j] * x[j]; }
            n2 += __shfl_xor_sync(0xffffffffu, n2, 1);
            n2 += __shfl_xor_sync(0xffffffffu, n2, 2);
            n2 += __shfl_xor_sync(0xffffffffu, n2, 4);

            const float norm = fmaxf(sqrtf(n2), 1e-15f);
            const float scl  = (norm > maxnorm) ? (maxnorm / norm) : 1.f;
            const float xn   = fmaxf(norm * scl, 1e-15f);
            float tk;
            if (hyp) {
                const float u_ = atanhf(fminf(sk * xn, 1.f - 1e-7f));
                tk = tanhf(0.5f * u_) / sk;
            } else {
                const float u_ = atanf(sk * xn);
                tk = tanf(0.5f * u_) / sk;
            }
            const float s2   = tk / xn;
            const float nrm2 = fmaxf(fabsf(tk), 1e-15f);
            const float scl2 = (nrm2 > maxnorm) ? (maxnorm / nrm2) : 1.f;
            const float st   = scl * s2 * scl2;

            float* o = Op + (size_t)n * DH + e0;
            *(float4*)(o)     = make_float4(x[0]*st, x[1]*st, x[2]*st, x[3]*st);
            *(float4*)(o + 4) = make_float4(x[4]*st, x[5]*st, x[6]*st, x[7]*st);
        }
        __syncthreads();
    }
}

extern "C" void kernel_launch(void* const* d_in, const int* in_sizes, int n_in,
                              void* d_out, int out_size)
{
    const float* Q    = (const float*)d_in[0];
    const float* K    = (const float*)d_in[1];
    const float* V    = (const float*)d_in[2];
    const float* mask = (const float*)d_in[3];
    const float* c    = (const float*)d_in[4];
    const int csize = in_sizes[4];
    const int N     = in_sizes[3];
    const int BH    = in_sizes[0] / (N * DH);

    int splits = NSPLIT;
    while (splits > 1 && (N % (splits * 32) != 0)) splits >>= 1;
    int chunks = NSPLIT;
    while (chunks > 1 && (N % (chunks * 128) != 0)) chunks >>= 1;

    cudaFuncSetAttribute(ctx_kernel, cudaFuncAttributeMaxDynamicSharedMemorySize,
                         K1_FLOATS * sizeof(float));
    cudaFuncSetAttribute(out_kernel, cudaFuncAttributeMaxDynamicSharedMemorySize,
                         K2_FLOATS * sizeof(float));

    dim3 g1(splits, BH);
    ctx_kernel<<<g1, 256, K1_FLOATS * sizeof(float)>>>(K, V, mask, c, csize, N);
    dim3 g2(chunks, BH);
    out_kernel<<<g2, 256, K2_FLOATS * sizeof(float)>>>(Q, c, csize, N, splits, (float*)d_out);
}

// round 8
// speedup vs baseline: 1.0852x; 1.0852x over previous
#include <cuda_runtime.h>

#define DH 64
#define MAX_BH 128
#define MAX_N 8192
#define NSPLIT 8

// ---- scratch (static __device__: no allocation) ----
__device__ float g_ctxp[NSPLIT * MAX_BH * DH * DH];  // per-split ctx partials
__device__ float g_vsump[NSPLIT * MAX_BH * DH];      // per-split vsum partials
__device__ float g_rinv[MAX_BH * MAX_N];             // per-row 1/denom (from V)

typedef unsigned long long u64t;

__device__ __forceinline__ u64t pk2(float lo, float hi) {
    u64t r; asm("mov.b64 %0, {%1, %2};" : "=l"(r) : "f"(lo), "f"(hi)); return r;
}
__device__ __forceinline__ void upk2(u64t v, float& lo, float& hi) {
    asm("mov.b64 {%0, %1}, %2;" : "=f"(lo), "=f"(hi) : "l"(v));
}
__device__ __forceinline__ void fma2(u64t& acc, u64t a, u64t b) {
    asm("fma.rn.f32x2 %0, %1, %2, %0;" : "+l"(acc) : "l"(a), "l"(b));
}
__device__ __forceinline__ float elu1(float v) { return v > 0.f ? v + 1.f : __expf(v); }

__device__ __forceinline__ unsigned smem_u32(const void* p) {
    return (unsigned)__cvta_generic_to_shared(p);
}
__device__ __forceinline__ void cp16(unsigned s, const float* g) {
    asm volatile("cp.async.cg.shared.global [%0], [%1], 16;" :: "r"(s), "l"(g));
}
#define CP_COMMIT() asm volatile("cp.async.commit_group;" ::: "memory")
#define CP_WAIT(n)  asm volatile("cp.async.wait_group %0;" :: "n"(n) : "memory")

// ===========================================================================
// K1 (round-4 measured best: 81.6us): ctx/vsum accumulation + rinv stash.
// Two-barrier pipeline, cp.async double-buffered K/V/mask staging,
// 8d x 8e thread tiles on dup/padded smem layouts, 2 CTAs/SM.
// ===========================================================================
#define K1_STV   0            // 2*32*68 = 4352
#define K1_STK   4352         // 4352
#define K1_STM   8704         // 64
#define K1_V2D   8768         // 32*160 = 5120 (dup v2)
#define K1_XS    13888        // 32*96 = 3072 (raw x)
#define K1_FLOATS 16960       // 67840 bytes

__global__ void __launch_bounds__(256, 2)
ctx_kernel(const float* __restrict__ Kg, const float* __restrict__ Vg,
           const float* __restrict__ mask, const float* __restrict__ c,
           int csize, int N)
{
    extern __shared__ float sm[];
    float* stV = sm + K1_STV;
    float* stK = sm + K1_STK;
    float* stM = sm + K1_STM;
    float* v2d = sm + K1_V2D;
    float* x_s = sm + K1_XS;

    const int split = blockIdx.x, bh = blockIdx.y;
    const int rows  = N / gridDim.x;
    const int n0    = split * rows;
    const float k   = (csize > 1) ? c[bh % csize] : c[0];

    const int tid   = threadIdx.x;
    const int lrow  = tid >> 3;
    const int lcol8 = tid & 7;
    const int wid   = tid >> 5, lane = tid & 31;
    const int pairid = wid >> 1, dhalf = wid & 1;
    const int dgrp = lane >> 3, egrp = lane & 7;
    const int gd   = dhalf * 4 + dgrp;

    const float* Kp = Kg + (size_t)bh * N * DH;
    const float* Vp = Vg + (size_t)bh * N * DH;

    const int pr_r0  = tid >> 4;
    const int pr_off = (tid & 15) * 4;

    auto prefetch = [&](int t0, int p) {
        const float* gv = Vp + (size_t)(n0 + t0) * DH;
        const float* gk = Kp + (size_t)(n0 + t0) * DH;
        const unsigned sv = smem_u32(stV + p * 2176);
        const unsigned sk = smem_u32(stK + p * 2176);
        cp16(sv + (pr_r0 * 68 + pr_off) * 4,        gv + pr_r0 * DH + pr_off);
        cp16(sv + ((pr_r0 + 16) * 68 + pr_off) * 4, gv + (pr_r0 + 16) * DH + pr_off);
        cp16(sk + (pr_r0 * 68 + pr_off) * 4,        gk + pr_r0 * DH + pr_off);
        cp16(sk + ((pr_r0 + 16) * 68 + pr_off) * 4, gk + (pr_r0 + 16) * DH + pr_off);
        if (tid < 8) cp16(smem_u32(stM + p * 32) + tid * 16, mask + n0 + t0 + tid * 4);
    };

    u64t acc[8][4] = {};
    float vsum[8] = {0.f,0.f,0.f,0.f,0.f,0.f,0.f,0.f};

    const int T = rows / 32;
    prefetch(0, 0);
    CP_COMMIT();

    for (int t = 0; t < T; t++) {
        const int p = t & 1;
        if (t + 1 < T) { prefetch((t + 1) * 32, p ^ 1); CP_COMMIT(); CP_WAIT(1); }
        else           { CP_WAIT(0); }
        __syncthreads();   // stage[p] visible; prior GEMM done with v2d/x_s

        // ---- elementwise from stage ----
        const int n = n0 + t * 32 + lrow;
        const float* vr = stV + p * 2176 + lrow * 68 + lcol8 * 8;
        const float4 va = *(const float4*)vr;
        const float4 vb = *(const float4*)(vr + 4);
        float ss = va.x*va.x + va.y*va.y + va.z*va.z + va.w*va.w
                 + vb.x*vb.x + vb.y*vb.y + vb.z*vb.z + vb.w*vb.w;
        ss += __shfl_xor_sync(0xffffffffu, ss, 1);
        ss += __shfl_xor_sync(0xffffffffu, ss, 2);
        ss += __shfl_xor_sync(0xffffffffu, ss, 4);
        const float denom = fmaxf(fmaf(k, ss, 1.f), 1e-15f);
        const float rinv  = 1.f / denom;
        const float g     = 2.f * rinv;
        const float gm1   = g - 1.f;
        const float sgn   = (gm1 >= 0.f) ? 1.f : -1.f;
        const float d2    = sgn * fmaxf(fabsf(gm1), 1e-10f);
        const float m     = stM[p * 32 + lrow];
        const float xs    = g / d2 * m;
        const float d2m   = d2 * m;

        float* xw = &x_s[lrow * 96 + lcol8 * 12];
        *(float4*)(xw)     = make_float4(va.x*xs, va.y*xs, va.z*xs, va.w*xs);
        *(float4*)(xw + 4) = make_float4(vb.x*xs, vb.y*xs, vb.z*xs, vb.w*xs);

        const float* kr = stK + p * 2176 + lrow * 68 + lcol8 * 8;
        const float4 ka = *(const float4*)kr;
        const float4 kb = *(const float4*)(kr + 4);
        float w[8];
        w[0] = d2m*elu1(ka.x*rinv); w[1] = d2m*elu1(ka.y*rinv);
        w[2] = d2m*elu1(ka.z*rinv); w[3] = d2m*elu1(ka.w*rinv);
        w[4] = d2m*elu1(kb.x*rinv); w[5] = d2m*elu1(kb.y*rinv);
        w[6] = d2m*elu1(kb.z*rinv); w[7] = d2m*elu1(kb.w*rinv);
        float* vw = &v2d[lrow * 160 + lcol8 * 20];
        *(float4*)(vw)      = make_float4(w[0], w[0], w[1], w[1]);
        *(float4*)(vw + 4)  = make_float4(w[2], w[2], w[3], w[3]);
        *(float4*)(vw + 8)  = make_float4(w[4], w[4], w[5], w[5]);
        *(float4*)(vw + 12) = make_float4(w[6], w[6], w[7], w[7]);
        #pragma unroll
        for (int j = 0; j < 8; j++) vsum[j] += w[j];

        if (lcol8 == 0) g_rinv[(size_t)bh * N + n] = rinv;
        __syncthreads();

        // ---- GEMM: 8 rank-1 updates per warp-pair, 8x8 per thread ----
        #pragma unroll
        for (int tt8 = 0; tt8 < 8; tt8++) {
            const int tt = pairid * 8 + tt8;
            const ulonglong2* ap = (const ulonglong2*)&v2d[tt * 160 + gd * 20];
            const ulonglong2 a01 = ap[0], a23 = ap[1], a45 = ap[2], a67 = ap[3];
            const ulonglong2* bp = (const ulonglong2*)&x_s[tt * 96 + egrp * 12];
            const ulonglong2 b03 = bp[0], b47 = bp[1];
            const u64t A[8] = {a01.x, a01.y, a23.x, a23.y, a45.x, a45.y, a67.x, a67.y};
            const u64t B[4] = {b03.x, b03.y, b47.x, b47.y};
            #pragma unroll
            for (int dd = 0; dd < 8; dd++) {
                fma2(acc[dd][0], A[dd], B[0]);
                fma2(acc[dd][1], A[dd], B[1]);
                fma2(acc[dd][2], A[dd], B[2]);
                fma2(acc[dd][3], A[dd], B[3]);
            }
        }
    }
    __syncthreads();

    // ---- reduce the 4 warp-pair copies via smem, write split partial ----
    float* red = v2d;
    #pragma unroll
    for (int p = 0; p < 4; p++) {
        if (pairid == p) {
            #pragma unroll
            for (int dd = 0; dd < 8; dd++) {
                #pragma unroll
                for (int ee = 0; ee < 4; ee++) {
                    float f0, f1; upk2(acc[dd][ee], f0, f1);
                    const int idx = (gd * 8 + dd) * 64 + egrp * 8 + ee * 2;
                    if (p == 0) { red[idx] = f0; red[idx + 1] = f1; }
                    else        { red[idx] += f0; red[idx + 1] += f1; }
                }
            }
        }
        __syncthreads();
    }
    float* dst = g_ctxp + ((size_t)bh * NSPLIT + split) * (DH * DH);
    for (int i = tid; i < DH * DH; i += 256) dst[i] = red[i];

    // ---- vsum partial ----
    float* vb2 = x_s;
    #pragma unroll
    for (int j = 0; j < 8; j++) vb2[lrow * 64 + lcol8 * 8 + j] = vsum[j];
    __syncthreads();
    if (tid < DH) {
        float s = 0.f;
        #pragma unroll
        for (int r = 0; r < 32; r++) s += vb2[r * 64 + tid];
        g_vsump[((size_t)bh * NSPLIT + split) * DH + tid] = s;
    }
}

// ===========================================================================
// K2 (round-5 measured best: 100.3us): fused split-reduce prologue +
// per-row X = (v1@ctx)/(v1.vsum) + geometry. 128-row tiles, 4n x 8e tiles.
// v1 raw stride 70 (banks {0,24,16,8}); ctx group-padded stride 96; 3 CTAs/SM.
// ===========================================================================
#define V1S 70
#define K2_CTX  0                 // 64*96 = 6144
#define K2_V1   6144              // 128*70 = 8960
#define K2_DP   15104             // 128
#define K2_VS   15232             // 64
#define K2_FLOATS 15296           // 61184 bytes

__global__ void __launch_bounds__(256, 3)
out_kernel(const float* __restrict__ Qg, const float* __restrict__ c,
           int csize, int N, int splits, float* __restrict__ out)
{
    extern __shared__ float sm[];
    float* ctx_s = sm + K2_CTX;
    float* v1s   = sm + K2_V1;
    float* dpbuf = sm + K2_DP;
    float* vs_s  = sm + K2_VS;

    const int chunk = blockIdx.x, bh = blockIdx.y;
    const int rows  = N / gridDim.x;
    const int n0    = chunk * rows;
    const float k   = (csize > 1) ? c[bh % csize] : c[0];
    const float sk  = sqrtf(fabsf(k) + 1e-15f);
    const float maxnorm = (k < 0.f) ? (1.f - 0.004f) / sk : 1e15f;
    const bool  hyp = (k < 0.f);

    const int tid   = threadIdx.x;
    const int lrow  = tid >> 3, lcol8 = tid & 7;
    const int wid   = tid >> 5, lane = tid & 31;
    const int rgrp  = lane >> 3, egrp = lane & 7;
    const int e0    = egrp * 8;

    const float* Qp = Qg + (size_t)bh * N * DH;
    const float* rv = g_rinv + (size_t)bh * N;
    float*       Op = out + (size_t)bh * N * DH;

    // ---- fused reduce of K1 split partials (L2-hot) ----
    const float* bctx = g_ctxp + (size_t)bh * NSPLIT * DH * DH;
    for (int i = tid; i < DH * DH; i += 256) {
        float s = 0.f;
        for (int p = 0; p < splits; p++) s += bctx[p * DH * DH + i];
        const int d = i >> 6, e = i & 63;
        ctx_s[d * 96 + (e >> 3) * 12 + (e & 7)] = s;
    }
    if (tid < DH) {
        float s = 0.f;
        for (int p = 0; p < splits; p++) s += g_vsump[((size_t)bh * NSPLIT + p) * DH + tid];
        vs_s[tid] = s;
    }
    __syncthreads();

    const int nIter = rows / 128;
    for (int it = 0; it < nIter; it++) {
        const int base = n0 + it * 128;

        // ---- elementwise: v1 = elu(Q*rinv)+1 (raw store), dp = v1.vsum ----
        #pragma unroll
        for (int s = 0; s < 4; s++) {
            const int lr = s * 32 + lrow;
            const int n  = base + lr;
            const float rinv = rv[n];
            const size_t nb = (size_t)n * DH + lcol8 * 8;
            const float4 qa = *(const float4*)(Qp + nb);
            const float4 qb = *(const float4*)(Qp + nb + 4);
            float v1v[8];
            v1v[0] = elu1(qa.x*rinv); v1v[1] = elu1(qa.y*rinv);
            v1v[2] = elu1(qa.z*rinv); v1v[3] = elu1(qa.w*rinv);
            v1v[4] = elu1(qb.x*rinv); v1v[5] = elu1(qb.y*rinv);
            v1v[6] = elu1(qb.z*rinv); v1v[7] = elu1(qb.w*rinv);

            const int vc = lcol8 * 8;
            float dp = v1v[0]*vs_s[vc+0] + v1v[1]*vs_s[vc+1]
                     + v1v[2]*vs_s[vc+2] + v1v[3]*vs_s[vc+3]
                     + v1v[4]*vs_s[vc+4] + v1v[5]*vs_s[vc+5]
                     + v1v[6]*vs_s[vc+6] + v1v[7]*vs_s[vc+7];
            dp += __shfl_xor_sync(0xffffffffu, dp, 1);
            dp += __shfl_xor_sync(0xffffffffu, dp, 2);
            dp += __shfl_xor_sync(0xffffffffu, dp, 4);

            float* vw = &v1s[lr * V1S + vc];
            *(float2*)(vw)     = make_float2(v1v[0], v1v[1]);
            *(float2*)(vw + 2) = make_float2(v1v[2], v1v[3]);
            *(float2*)(vw + 4) = make_float2(v1v[4], v1v[5]);
            *(float2*)(vw + 6) = make_float2(v1v[6], v1v[7]);
            if (lcol8 == 0) dpbuf[lr] = dp;
        }
        __syncthreads();

        // ---- GEMV: thread = 4 rows x 8 e ----
        const int row0 = wid * 16 + rgrp * 4;
        u64t acc[4][4] = {};
        #pragma unroll
        for (int d = 0; d < DH; d += 2) {
            const ulonglong2* bp0 = (const ulonglong2*)&ctx_s[d * 96 + egrp * 12];
            const ulonglong2* bp1 = (const ulonglong2*)&ctx_s[(d + 1) * 96 + egrp * 12];
            const ulonglong2 bA = bp0[0], bB = bp0[1];
            const ulonglong2 cA = bp1[0], cB = bp1[1];
            #pragma unroll
            for (int rr = 0; rr < 4; rr++) {
                const u64t ar = *(const u64t*)&v1s[(row0 + rr) * V1S + d];
                float a0, a1; upk2(ar, a0, a1);
                const u64t aa0 = pk2(a0, a0), aa1 = pk2(a1, a1);
                fma2(acc[rr][0], aa0, bA.x); fma2(acc[rr][1], aa0, bA.y);
                fma2(acc[rr][2], aa0, bB.x); fma2(acc[rr][3], aa0, bB.y);
                fma2(acc[rr][0], aa1, cA.x); fma2(acc[rr][1], aa1, cA.y);
                fma2(acc[rr][2], aa1, cB.x); fma2(acc[rr][3], aa1, cB.y);
            }
        }

        // ---- tail: Dinv scale, project -> mobius(0.5) -> project, store ----
        #pragma unroll
        for (int rr = 0; rr < 4; rr++) {
            const int lr = row0 + rr;
            const int n  = base + lr;
            float x[8];
            upk2(acc[rr][0], x[0], x[1]); upk2(acc[rr][1], x[2], x[3]);
            upk2(acc[rr][2], x[4], x[5]); upk2(acc[rr][3], x[6], x[7]);

            const float dp = dpbuf[lr];
            const float Dinv = 1.f / ((dp == 0.f) ? 1e-5f : dp);
            float n2 = 0.f;
            #pragma unroll
            for (int j = 0; j < 8; j++) { x[j] *= Dinv; n2 += x[j] * x[j]; }
            n2 += __shfl_xor_sync(0xffffffffu, n2, 1);
            n2 += __shfl_xor_sync(0xffffffffu, n2, 2);
            n2 += __shfl_xor_sync(0xffffffffu, n2, 4);

            const float norm = fmaxf(sqrtf(n2), 1e-15f);
            const float scl  = (norm > maxnorm) ? (maxnorm / norm) : 1.f;
            const float xn   = fmaxf(norm * scl, 1e-15f);
            float tk;
            if (hyp) {
                const float u_ = atanhf(fminf(sk * xn, 1.f - 1e-7f));
                tk = tanhf(0.5f * u_) / sk;
            } else {
                const float u_ = atanf(sk * xn);
                tk = tanf(0.5f * u_) / sk;
            }
            const float s2   = tk / xn;
            const float nrm2 = fmaxf(fabsf(tk), 1e-15f);
            const float scl2 = (nrm2 > maxnorm) ? (maxnorm / nrm2) : 1.f;
            const float st   = scl * s2 * scl2;

            float* o = Op + (size_t)n * DH + e0;
            *(float4*)(o)     = make_float4(x[0]*st, x[1]*st, x[2]*st, x[3]*st);
            *(float4*)(o + 4) = make_float4(x[4]*st, x[5]*st, x[6]*st, x[7]*st);
        }
        __syncthreads();
    }
}

extern "C" void kernel_launch(void* const* d_in, const int* in_sizes, int n_in,
                              void* d_out, int out_size)
{
    const float* Q    = (const float*)d_in[0];
    const float* K    = (const float*)d_in[1];
    const float* V    = (const float*)d_in[2];
    const float* mask = (const float*)d_in[3];
    const float* c    = (const float*)d_in[4];
    const int csize = in_sizes[4];
    const int N     = in_sizes[3];
    const int BH    = in_sizes[0] / (N * DH);

    int splits = NSPLIT;
    while (splits > 1 && (N % (splits * 32) != 0)) splits >>= 1;
    int chunks = NSPLIT;
    while (chunks > 1 && (N % (chunks * 128) != 0)) chunks >>= 1;

    cudaFuncSetAttribute(ctx_kernel, cudaFuncAttributeMaxDynamicSharedMemorySize,
                         K1_FLOATS * sizeof(float));
    cudaFuncSetAttribute(out_kernel, cudaFuncAttributeMaxDynamicSharedMemorySize,
                         K2_FLOATS * sizeof(float));

    dim3 g1(splits, BH);
    ctx_kernel<<<g1, 256, K1_FLOATS * sizeof(float)>>>(K, V, mask, c, csize, N);
    dim3 g2(chunks, BH);
    out_kernel<<<g2, 256, K2_FLOATS * sizeof(float)>>>(Q, c, csize, N, splits, (float*)d_out);
}

// round 9
// speedup vs baseline: 1.0856x; 1.0003x over previous
#include <cuda_runtime.h>

#define DH 64
#define MAX_BH 128
#define MAX_N 8192
#define NSPLIT 8

// ---- scratch (static __device__: no allocation) ----
__device__ float g_ctxp[NSPLIT * MAX_BH * DH * DH];  // per-split ctx partials
__device__ float g_vsump[NSPLIT * MAX_BH * DH];      // per-split vsum partials
__device__ float g_rinv[MAX_BH * MAX_N];             // per-row 1/denom (from V)

typedef unsigned long long u64t;

__device__ __forceinline__ u64t pk2(float lo, float hi) {
    u64t r; asm("mov.b64 %0, {%1, %2};" : "=l"(r) : "f"(lo), "f"(hi)); return r;
}
__device__ __forceinline__ void upk2(u64t v, float& lo, float& hi) {
    asm("mov.b64 {%0, %1}, %2;" : "=f"(lo), "=f"(hi) : "l"(v));
}
__device__ __forceinline__ void fma2(u64t& acc, u64t a, u64t b) {
    asm("fma.rn.f32x2 %0, %1, %2, %0;" : "+l"(acc) : "l"(a), "l"(b));
}
__device__ __forceinline__ float elu1(float v) { return v > 0.f ? v + 1.f : __expf(v); }

__device__ __forceinline__ unsigned smem_u32(const void* p) {
    return (unsigned)__cvta_generic_to_shared(p);
}
__device__ __forceinline__ void cp16(unsigned s, const float* g) {
    asm volatile("cp.async.cg.shared.global [%0], [%1], 16;" :: "r"(s), "l"(g));
}
#define CP_COMMIT() asm volatile("cp.async.commit_group;" ::: "memory")
#define CP_WAIT(n)  asm volatile("cp.async.wait_group %0;" :: "n"(n) : "memory")

// ===========================================================================
// K1 (round-4 pipeline, 81.6us): ctx/vsum accumulation + rinv stash.
// Two-barrier pipeline, cp.async double-buffered K/V/mask staging,
// 8d x 8e thread tiles on dup/padded smem layouts, 2 CTAs/SM.
// Epilogue: parallel 4-copy reduce over the dead stage buffers.
// ===========================================================================
#define K1_STV   0            // 2*32*68 = 4352
#define K1_STK   4352         // 4352
#define K1_STM   8704         // 64
#define K1_V2D   8768         // 32*160 = 5120 (dup v2)
#define K1_XS    13888        // 32*96 = 3072 (raw x)
#define K1_FLOATS 16960       // 67840 bytes

__global__ void __launch_bounds__(256, 2)
ctx_kernel(const float* __restrict__ Kg, const float* __restrict__ Vg,
           const float* __restrict__ mask, const float* __restrict__ c,
           int csize, int N)
{
    extern __shared__ float sm[];
    float* stV = sm + K1_STV;
    float* stK = sm + K1_STK;
    float* stM = sm + K1_STM;
    float* v2d = sm + K1_V2D;
    float* x_s = sm + K1_XS;

    const int split = blockIdx.x, bh = blockIdx.y;
    const int rows  = N / gridDim.x;
    const int n0    = split * rows;
    const float k   = (csize > 1) ? c[bh % csize] : c[0];

    const int tid   = threadIdx.x;
    const int lrow  = tid >> 3;
    const int lcol8 = tid & 7;
    const int wid   = tid >> 5, lane = tid & 31;
    const int pairid = wid >> 1, dhalf = wid & 1;
    const int dgrp = lane >> 3, egrp = lane & 7;
    const int gd   = dhalf * 4 + dgrp;

    const float* Kp = Kg + (size_t)bh * N * DH;
    const float* Vp = Vg + (size_t)bh * N * DH;

    const int pr_r0  = tid >> 4;
    const int pr_off = (tid & 15) * 4;

    auto prefetch = [&](int t0, int p) {
        const float* gv = Vp + (size_t)(n0 + t0) * DH;
        const float* gk = Kp + (size_t)(n0 + t0) * DH;
        const unsigned sv = smem_u32(stV + p * 2176);
        const unsigned sk = smem_u32(stK + p * 2176);
        cp16(sv + (pr_r0 * 68 + pr_off) * 4,        gv + pr_r0 * DH + pr_off);
        cp16(sv + ((pr_r0 + 16) * 68 + pr_off) * 4, gv + (pr_r0 + 16) * DH + pr_off);
        cp16(sk + (pr_r0 * 68 + pr_off) * 4,        gk + pr_r0 * DH + pr_off);
        cp16(sk + ((pr_r0 + 16) * 68 + pr_off) * 4, gk + (pr_r0 + 16) * DH + pr_off);
        if (tid < 8) cp16(smem_u32(stM + p * 32) + tid * 16, mask + n0 + t0 + tid * 4);
    };

    u64t acc[8][4] = {};
    float vsum[8] = {0.f,0.f,0.f,0.f,0.f,0.f,0.f,0.f};

    const int T = rows / 32;
    prefetch(0, 0);
    CP_COMMIT();

    for (int t = 0; t < T; t++) {
        const int p = t & 1;
        if (t + 1 < T) { prefetch((t + 1) * 32, p ^ 1); CP_COMMIT(); CP_WAIT(1); }
        else           { CP_WAIT(0); }
        __syncthreads();   // stage[p] visible; prior GEMM done with v2d/x_s

        // ---- elementwise from stage ----
        const int n = n0 + t * 32 + lrow;
        const float* vr = stV + p * 2176 + lrow * 68 + lcol8 * 8;
        const float4 va = *(const float4*)vr;
        const float4 vb = *(const float4*)(vr + 4);
        float ss = va.x*va.x + va.y*va.y + va.z*va.z + va.w*va.w
                 + vb.x*vb.x + vb.y*vb.y + vb.z*vb.z + vb.w*vb.w;
        ss += __shfl_xor_sync(0xffffffffu, ss, 1);
        ss += __shfl_xor_sync(0xffffffffu, ss, 2);
        ss += __shfl_xor_sync(0xffffffffu, ss, 4);
        const float denom = fmaxf(fmaf(k, ss, 1.f), 1e-15f);
        const float rinv  = 1.f / denom;
        const float g     = 2.f * rinv;
        const float gm1   = g - 1.f;
        const float sgn   = (gm1 >= 0.f) ? 1.f : -1.f;
        const float d2    = sgn * fmaxf(fabsf(gm1), 1e-10f);
        const float m     = stM[p * 32 + lrow];
        const float xs    = g / d2 * m;
        const float d2m   = d2 * m;

        float* xw = &x_s[lrow * 96 + lcol8 * 12];
        *(float4*)(xw)     = make_float4(va.x*xs, va.y*xs, va.z*xs, va.w*xs);
        *(float4*)(xw + 4) = make_float4(vb.x*xs, vb.y*xs, vb.z*xs, vb.w*xs);

        const float* kr = stK + p * 2176 + lrow * 68 + lcol8 * 8;
        const float4 ka = *(const float4*)kr;
        const float4 kb = *(const float4*)(kr + 4);
        float w[8];
        w[0] = d2m*elu1(ka.x*rinv); w[1] = d2m*elu1(ka.y*rinv);
        w[2] = d2m*elu1(ka.z*rinv); w[3] = d2m*elu1(ka.w*rinv);
        w[4] = d2m*elu1(kb.x*rinv); w[5] = d2m*elu1(kb.y*rinv);
        w[6] = d2m*elu1(kb.z*rinv); w[7] = d2m*elu1(kb.w*rinv);
        float* vw = &v2d[lrow * 160 + lcol8 * 20];
        *(float4*)(vw)      = make_float4(w[0], w[0], w[1], w[1]);
        *(float4*)(vw + 4)  = make_float4(w[2], w[2], w[3], w[3]);
        *(float4*)(vw + 8)  = make_float4(w[4], w[4], w[5], w[5]);
        *(float4*)(vw + 12) = make_float4(w[6], w[6], w[7], w[7]);
        #pragma unroll
        for (int j = 0; j < 8; j++) vsum[j] += w[j];

        if (lcol8 == 0) g_rinv[(size_t)bh * N + n] = rinv;
        __syncthreads();

        // ---- GEMM: 8 rank-1 updates per warp-pair, 8x8 per thread ----
        #pragma unroll
        for (int tt8 = 0; tt8 < 8; tt8++) {
            const int tt = pairid * 8 + tt8;
            const ulonglong2* ap = (const ulonglong2*)&v2d[tt * 160 + gd * 20];
            const ulonglong2 a01 = ap[0], a23 = ap[1], a45 = ap[2], a67 = ap[3];
            const ulonglong2* bp = (const ulonglong2*)&x_s[tt * 96 + egrp * 12];
            const ulonglong2 b03 = bp[0], b47 = bp[1];
            const u64t A[8] = {a01.x, a01.y, a23.x, a23.y, a45.x, a45.y, a67.x, a67.y};
            const u64t B[4] = {b03.x, b03.y, b47.x, b47.y};
            #pragma unroll
            for (int dd = 0; dd < 8; dd++) {
                fma2(acc[dd][0], A[dd], B[0]);
                fma2(acc[dd][1], A[dd], B[1]);
                fma2(acc[dd][2], A[dd], B[2]);
                fma2(acc[dd][3], A[dd], B[3]);
            }
        }
    }
    __syncthreads();   // GEMM done; ALL smem (stages included) now dead

    // ---- epilogue: all 4 pair-copies written in parallel, then tree-sum ----
    {
        float* reg0 = sm + pairid * 4096;   // disjoint per pair
        #pragma unroll
        for (int dd = 0; dd < 8; dd++) {
            #pragma unroll
            for (int ee = 0; ee < 4; ee++) {
                float f0, f1; upk2(acc[dd][ee], f0, f1);
                const int idx = (gd * 8 + dd) * 64 + egrp * 8 + ee * 2;
                reg0[idx]     = f0;
                reg0[idx + 1] = f1;
            }
        }
    }
    __syncthreads();
    float* dst = g_ctxp + ((size_t)bh * NSPLIT + split) * (DH * DH);
    for (int i = tid; i < DH * DH; i += 256)
        dst[i] = sm[i] + sm[4096 + i] + sm[8192 + i] + sm[12288 + i];
    __syncthreads();   // reads done before vsum reuses region 0

    // ---- vsum partial ----
    #pragma unroll
    for (int j = 0; j < 8; j++) sm[lrow * 64 + lcol8 * 8 + j] = vsum[j];
    __syncthreads();
    if (tid < DH) {
        float s = 0.f;
        #pragma unroll
        for (int r = 0; r < 32; r++) s += sm[r * 64 + tid];
        g_vsump[((size_t)bh * NSPLIT + split) * DH + tid] = s;
    }
}

// ===========================================================================
// K2 (round-5 shape + half-angle tail): fused split-reduce prologue +
// per-row X = (v1@ctx)/(v1.vsum) + geometry. 128-row tiles, 4n x 8e tiles.
// v1 raw stride 70 (banks {0,24,16,8}); ctx group-padded stride 96; 3 CTAs/SM.
// Mobius tail uses tanh(atanh(y)/2) = y/(1+sqrt(1-y^2)) — no libm.
// ===========================================================================
#define V1S 70
#define K2_CTX  0                 // 64*96 = 6144
#define K2_V1   6144              // 128*70 = 8960
#define K2_DP   15104             // 128
#define K2_VS   15232             // 64
#define K2_FLOATS 15296           // 61184 bytes

__global__ void __launch_bounds__(256, 3)
out_kernel(const float* __restrict__ Qg, const float* __restrict__ c,
           int csize, int N, int splits, float* __restrict__ out)
{
    extern __shared__ float sm[];
    float* ctx_s = sm + K2_CTX;
    float* v1s   = sm + K2_V1;
    float* dpbuf = sm + K2_DP;
    float* vs_s  = sm + K2_VS;

    const int chunk = blockIdx.x, bh = blockIdx.y;
    const int rows  = N / gridDim.x;
    const int n0    = chunk * rows;
    const float k   = (csize > 1) ? c[bh % csize] : c[0];
    const float sk  = sqrtf(fabsf(k) + 1e-15f);
    const float maxnorm = (k < 0.f) ? (1.f - 0.004f) / sk : 1e15f;
    const bool  hyp = (k < 0.f);

    const int tid   = threadIdx.x;
    const int lrow  = tid >> 3, lcol8 = tid & 7;
    const int wid   = tid >> 5, lane = tid & 31;
    const int rgrp  = lane >> 3, egrp = lane & 7;
    const int e0    = egrp * 8;

    const float* Qp = Qg + (size_t)bh * N * DH;
    const float* rv = g_rinv + (size_t)bh * N;
    float*       Op = out + (size_t)bh * N * DH;

    // ---- fused reduce of K1 split partials (L2-hot) ----
    const float* bctx = g_ctxp + (size_t)bh * NSPLIT * DH * DH;
    for (int i = tid; i < DH * DH; i += 256) {
        float s = 0.f;
        for (int p = 0; p < splits; p++) s += bctx[p * DH * DH + i];
        const int d = i >> 6, e = i & 63;
        ctx_s[d * 96 + (e >> 3) * 12 + (e & 7)] = s;
    }
    if (tid < DH) {
        float s = 0.f;
        for (int p = 0; p < splits; p++) s += g_vsump[((size_t)bh * NSPLIT + p) * DH + tid];
        vs_s[tid] = s;
    }
    __syncthreads();

    const int nIter = rows / 128;
    for (int it = 0; it < nIter; it++) {
        const int base = n0 + it * 128;

        // ---- elementwise: v1 = elu(Q*rinv)+1 (raw store), dp = v1.vsum ----
        #pragma unroll
        for (int s = 0; s < 4; s++) {
            const int lr = s * 32 + lrow;
            const int n  = base + lr;
            const float rinv = rv[n];
            const size_t nb = (size_t)n * DH + lcol8 * 8;
            const float4 qa = *(const float4*)(Qp + nb);
            const float4 qb = *(const float4*)(Qp + nb + 4);
            float v1v[8];
            v1v[0] = elu1(qa.x*rinv); v1v[1] = elu1(qa.y*rinv);
            v1v[2] = elu1(qa.z*rinv); v1v[3] = elu1(qa.w*rinv);
            v1v[4] = elu1(qb.x*rinv); v1v[5] = elu1(qb.y*rinv);
            v1v[6] = elu1(qb.z*rinv); v1v[7] = elu1(qb.w*rinv);

            const int vc = lcol8 * 8;
            float dp = v1v[0]*vs_s[vc+0] + v1v[1]*vs_s[vc+1]
                     + v1v[2]*vs_s[vc+2] + v1v[3]*vs_s[vc+3]
                     + v1v[4]*vs_s[vc+4] + v1v[5]*vs_s[vc+5]
                     + v1v[6]*vs_s[vc+6] + v1v[7]*vs_s[vc+7];
            dp += __shfl_xor_sync(0xffffffffu, dp, 1);
            dp += __shfl_xor_sync(0xffffffffu, dp, 2);
            dp += __shfl_xor_sync(0xffffffffu, dp, 4);

            float* vw = &v1s[lr * V1S + vc];
            *(float2*)(vw)     = make_float2(v1v[0], v1v[1]);
            *(float2*)(vw + 2) = make_float2(v1v[2], v1v[3]);
            *(float2*)(vw + 4) = make_float2(v1v[4], v1v[5]);
            *(float2*)(vw + 6) = make_float2(v1v[6], v1v[7]);
            if (lcol8 == 0) dpbuf[lr] = dp;
        }
        __syncthreads();

        // ---- GEMV: thread = 4 rows x 8 e ----
        const int row0 = wid * 16 + rgrp * 4;
        u64t acc[4][4] = {};
        #pragma unroll
        for (int d = 0; d < DH; d += 2) {
            const ulonglong2* bp0 = (const ulonglong2*)&ctx_s[d * 96 + egrp * 12];
            const ulonglong2* bp1 = (const ulonglong2*)&ctx_s[(d + 1) * 96 + egrp * 12];
            const ulonglong2 bA = bp0[0], bB = bp0[1];
            const ulonglong2 cA = bp1[0], cB = bp1[1];
            #pragma unroll
            for (int rr = 0; rr < 4; rr++) {
                const u64t ar = *(const u64t*)&v1s[(row0 + rr) * V1S + d];
                float a0, a1; upk2(ar, a0, a1);
                const u64t aa0 = pk2(a0, a0), aa1 = pk2(a1, a1);
                fma2(acc[rr][0], aa0, bA.x); fma2(acc[rr][1], aa0, bA.y);
                fma2(acc[rr][2], aa0, bB.x); fma2(acc[rr][3], aa0, bB.y);
                fma2(acc[rr][0], aa1, cA.x); fma2(acc[rr][1], aa1, cA.y);
                fma2(acc[rr][2], aa1, cB.x); fma2(acc[rr][3], aa1, cB.y);
            }
        }

        // ---- tail: Dinv scale, project -> mobius(0.5) -> project, store ----
        #pragma unroll
        for (int rr = 0; rr < 4; rr++) {
            const int lr = row0 + rr;
            const int n  = base + lr;
            float x[8];
            upk2(acc[rr][0], x[0], x[1]); upk2(acc[rr][1], x[2], x[3]);
            upk2(acc[rr][2], x[4], x[5]); upk2(acc[rr][3], x[6], x[7]);

            const float dp = dpbuf[lr];
            const float Dinv = 1.f / ((dp == 0.f) ? 1e-5f : dp);
            float n2 = 0.f;
            #pragma unroll
            for (int j = 0; j < 8; j++) { x[j] *= Dinv; n2 += x[j] * x[j]; }
            n2 += __shfl_xor_sync(0xffffffffu, n2, 1);
            n2 += __shfl_xor_sync(0xffffffffu, n2, 2);
            n2 += __shfl_xor_sync(0xffffffffu, n2, 4);

            const float norm = fmaxf(sqrtf(n2), 1e-15f);
            const float scl  = (norm > maxnorm) ? (maxnorm / norm) : 1.f;
            const float xn   = fmaxf(norm * scl, 1e-15f);
            // mobius scalar mul r=0.5 via half-angle identities (exact):
            //   k<0: tanh(atanh(y)/2) = y / (1 + sqrt(1 - y^2))
            //   k>0: tan(atan(z)/2)   = z / (1 + sqrt(1 + z^2))
            float tk;
            if (hyp) {
                const float y = fminf(sk * xn, 1.f - 1e-7f);
                tk = y / ((1.f + sqrtf(fmaxf(1.f - y * y, 0.f))) * sk);
            } else {
                const float z = sk * xn;
                tk = z / ((1.f + sqrtf(1.f + z * z)) * sk);
            }
            const float s2   = tk / xn;
            const float nrm2 = fmaxf(fabsf(tk), 1e-15f);
            const float scl2 = (nrm2 > maxnorm) ? (maxnorm / nrm2) : 1.f;
            const float st   = scl * s2 * scl2;

            float* o = Op + (size_t)n * DH + e0;
            *(float4*)(o)     = make_float4(x[0]*st, x[1]*st, x[2]*st, x[3]*st);
            *(float4*)(o + 4) = make_float4(x[4]*st, x[5]*st, x[6]*st, x[7]*st);
        }
        __syncthreads();
    }
}

extern "C" void kernel_launch(void* const* d_in, const int* in_sizes, int n_in,
                              void* d_out, int out_size)
{
    const float* Q    = (const float*)d_in[0];
    const float* K    = (const float*)d_in[1];
    const float* V    = (const float*)d_in[2];
    const float* mask = (const float*)d_in[3];
    const float* c    = (const float*)d_in[4];
    const int csize = in_sizes[4];
    const int N     = in_sizes[3];
    const int BH    = in_sizes[0] / (N * DH);

    int splits = NSPLIT;
    while (splits > 1 && (N % (splits * 32) != 0)) splits >>= 1;
    int chunks = NSPLIT;
    while (chunks > 1 && (N % (chunks * 128) != 0)) chunks >>= 1;

    cudaFuncSetAttribute(ctx_kernel, cudaFuncAttributeMaxDynamicSharedMemorySize,
                         K1_FLOATS * sizeof(float));
    cudaFuncSetAttribute(out_kernel, cudaFuncAttributeMaxDynamicSharedMemorySize,
                         K2_FLOATS * sizeof(float));

    dim3 g1(splits, BH);
    ctx_kernel<<<g1, 256, K1_FLOATS * sizeof(float)>>>(K, V, mask, c, csize, N);
    dim3 g2(chunks, BH);
    out_kernel<<<g2, 256, K2_FLOATS * sizeof(float)>>>(Q, c, csize, N, splits, (float*)d_out);
}

// round 10
// speedup vs baseline: 1.1918x; 1.0978x over previous
#include <cuda_runtime.h>

#define DH 64
#define MAX_BH 128
#define MAX_N 8192
#define NSPLIT 8

// ---- scratch (static __device__: no allocation) ----
__device__ float g_ctxp[NSPLIT * MAX_BH * DH * DH];  // per-split ctx partials
__device__ float g_vsump[NSPLIT * MAX_BH * DH];      // per-split vsum partials
__device__ float g_rinv[MAX_BH * MAX_N];             // per-row 1/denom (from V)

typedef unsigned long long u64t;

__device__ __forceinline__ u64t pk2(float lo, float hi) {
    u64t r; asm("mov.b64 %0, {%1, %2};" : "=l"(r) : "f"(lo), "f"(hi)); return r;
}
__device__ __forceinline__ void upk2(u64t v, float& lo, float& hi) {
    asm("mov.b64 {%0, %1}, %2;" : "=f"(lo), "=f"(hi) : "l"(v));
}
__device__ __forceinline__ void fma2(u64t& acc, u64t a, u64t b) {
    asm("fma.rn.f32x2 %0, %1, %2, %0;" : "+l"(acc) : "l"(a), "l"(b));
}
__device__ __forceinline__ float elu1(float v) { return v > 0.f ? v + 1.f : __expf(v); }

__device__ __forceinline__ unsigned smem_u32(const void* p) {
    return (unsigned)__cvta_generic_to_shared(p);
}
__device__ __forceinline__ void cp16(unsigned s, const float* g) {
    asm volatile("cp.async.cg.shared.global [%0], [%1], 16;" :: "r"(s), "l"(g));
}
#define CP_COMMIT() asm volatile("cp.async.commit_group;" ::: "memory")
#define CP_WAIT(n)  asm volatile("cp.async.wait_group %0;" :: "n"(n) : "memory")
#define PAIR_BAR(id) asm volatile("bar.sync %0, 64;" :: "r"(id) : "memory")

// ===========================================================================
// K1: ctx/vsum accumulation + rinv stash. PAIR-DECOUPLED: each warp-pair
// prefetches (self-consumed cp.async), EWs, and GEMMs ONLY its 8 rows per
// tile; block barriers replaced by named pair barriers -> 4 independent
// pipelines per CTA, stalls decorrelate.
// ===========================================================================
#define K1_STV   0            // 2*32*68 = 4352
#define K1_STK   4352         // 4352
#define K1_STM   8704         // 64
#define K1_V2D   8768         // 32*160 = 5120 (dup v2)
#define K1_XS    13888        // 32*96 = 3072 (raw x)
#define K1_FLOATS 16960       // 67840 bytes

__global__ void __launch_bounds__(256, 2)
ctx_kernel(const float* __restrict__ Kg, const float* __restrict__ Vg,
           const float* __restrict__ mask, const float* __restrict__ c,
           int csize, int N)
{
    extern __shared__ float sm[];
    float* stV = sm + K1_STV;
    float* stK = sm + K1_STK;
    float* stM = sm + K1_STM;
    float* v2d = sm + K1_V2D;
    float* x_s = sm + K1_XS;

    const int split = blockIdx.x, bh = blockIdx.y;
    const int rows  = N / gridDim.x;
    const int n0    = split * rows;
    const float k   = (csize > 1) ? c[bh % csize] : c[0];

    const int tid   = threadIdx.x;
    const int lrow  = tid >> 3;          // global row in tile (pair-local range)
    const int lcol8 = tid & 7;
    const int wid   = tid >> 5, lane = tid & 31;
    const int pairid = wid >> 1, dhalf = wid & 1;
    const int dgrp = lane >> 3, egrp = lane & 7;
    const int gd   = dhalf * 4 + dgrp;
    const int local = tid & 63;          // thread index within warp-pair

    const float* Kp = Kg + (size_t)bh * N * DH;
    const float* Vp = Vg + (size_t)bh * N * DH;

    // self-consumed prefetch: thread copies exactly the 8 floats (per array)
    // that IT will read in EW (row lrow, cols lcol8*8..+7)
    auto prefetch = [&](int t0, int p) {
        const size_t gb = (size_t)(n0 + t0 + lrow) * DH + lcol8 * 8;
        const unsigned so = (unsigned)((lrow * 68 + lcol8 * 8) * 4);
        const unsigned sv = smem_u32(stV + p * 2176) + so;
        const unsigned sk = smem_u32(stK + p * 2176) + so;
        cp16(sv,      Vp + gb);
        cp16(sv + 16, Vp + gb + 4);
        cp16(sk,      Kp + gb);
        cp16(sk + 16, Kp + gb + 4);
        if (local < 2)   // mask rows for this pair (8 floats = 2 cp16)
            cp16(smem_u32(stM + p * 32) + (pairid * 8 + local * 4) * 4,
                 mask + n0 + t0 + pairid * 8 + local * 4);
    };

    u64t acc[8][4] = {};
    float vsum[8] = {0.f,0.f,0.f,0.f,0.f,0.f,0.f,0.f};

    const int T = rows / 32;
    prefetch(0, 0);
    CP_COMMIT();

    for (int t = 0; t < T; t++) {
        const int p = t & 1;
        if (t + 1 < T) { prefetch((t + 1) * 32, p ^ 1); CP_COMMIT(); CP_WAIT(1); }
        else           { CP_WAIT(0); }
        PAIR_BAR(pairid + 1);   // pair's stage visible; pair's prev GEMM done

        // ---- elementwise from stage (own row) ----
        const int n = n0 + t * 32 + lrow;
        const float* vr = stV + p * 2176 + lrow * 68 + lcol8 * 8;
        const float4 va = *(const float4*)vr;
        const float4 vb = *(const float4*)(vr + 4);
        float ss = va.x*va.x + va.y*va.y + va.z*va.z + va.w*va.w
                 + vb.x*vb.x + vb.y*vb.y + vb.z*vb.z + vb.w*vb.w;
        ss += __shfl_xor_sync(0xffffffffu, ss, 1);
        ss += __shfl_xor_sync(0xffffffffu, ss, 2);
        ss += __shfl_xor_sync(0xffffffffu, ss, 4);
        const float denom = fmaxf(fmaf(k, ss, 1.f), 1e-15f);
        const float rinv  = 1.f / denom;
        const float g     = 2.f * rinv;
        const float gm1   = g - 1.f;
        const float sgn   = (gm1 >= 0.f) ? 1.f : -1.f;
        const float d2    = sgn * fmaxf(fabsf(gm1), 1e-10f);
        const float m     = stM[p * 32 + lrow];
        const float xs    = g / d2 * m;
        const float d2m   = d2 * m;

        float* xw = &x_s[lrow * 96 + lcol8 * 12];
        *(float4*)(xw)     = make_float4(va.x*xs, va.y*xs, va.z*xs, va.w*xs);
        *(float4*)(xw + 4) = make_float4(vb.x*xs, vb.y*xs, vb.z*xs, vb.w*xs);

        const float* kr = stK + p * 2176 + lrow * 68 + lcol8 * 8;
        const float4 ka = *(const float4*)kr;
        const float4 kb = *(const float4*)(kr + 4);
        float w[8];
        w[0] = d2m*elu1(ka.x*rinv); w[1] = d2m*elu1(ka.y*rinv);
        w[2] = d2m*elu1(ka.z*rinv); w[3] = d2m*elu1(ka.w*rinv);
        w[4] = d2m*elu1(kb.x*rinv); w[5] = d2m*elu1(kb.y*rinv);
        w[6] = d2m*elu1(kb.z*rinv); w[7] = d2m*elu1(kb.w*rinv);
        float* vw = &v2d[lrow * 160 + lcol8 * 20];
        *(float4*)(vw)      = make_float4(w[0], w[0], w[1], w[1]);
        *(float4*)(vw + 4)  = make_float4(w[2], w[2], w[3], w[3]);
        *(float4*)(vw + 8)  = make_float4(w[4], w[4], w[5], w[5]);
        *(float4*)(vw + 12) = make_float4(w[6], w[6], w[7], w[7]);
        #pragma unroll
        for (int j = 0; j < 8; j++) vsum[j] += w[j];

        if (lcol8 == 0) g_rinv[(size_t)bh * N + n] = rinv;
        PAIR_BAR(pairid + 1);   // pair's EW writes visible to pair's GEMM

        // ---- GEMM: 8 rank-1 updates on own pair's rows, 8x8 per thread ----
        #pragma unroll
        for (int tt8 = 0; tt8 < 8; tt8++) {
            const int tt = pairid * 8 + tt8;
            const ulonglong2* ap = (const ulonglong2*)&v2d[tt * 160 + gd * 20];
            const ulonglong2 a01 = ap[0], a23 = ap[1], a45 = ap[2], a67 = ap[3];
            const ulonglong2* bp = (const ulonglong2*)&x_s[tt * 96 + egrp * 12];
            const ulonglong2 b03 = bp[0], b47 = bp[1];
            const u64t A[8] = {a01.x, a01.y, a23.x, a23.y, a45.x, a45.y, a67.x, a67.y};
            const u64t B[4] = {b03.x, b03.y, b47.x, b47.y};
            #pragma unroll
            for (int dd = 0; dd < 8; dd++) {
                fma2(acc[dd][0], A[dd], B[0]);
                fma2(acc[dd][1], A[dd], B[1]);
                fma2(acc[dd][2], A[dd], B[2]);
                fma2(acc[dd][3], A[dd], B[3]);
            }
        }
    }
    __syncthreads();   // all pairs done; ALL smem now dead

    // ---- epilogue: all 4 pair-copies written in parallel, then tree-sum ----
    {
        float* reg0 = sm + pairid * 4096;   // disjoint per pair
        #pragma unroll
        for (int dd = 0; dd < 8; dd++) {
            #pragma unroll
            for (int ee = 0; ee < 4; ee++) {
                float f0, f1; upk2(acc[dd][ee], f0, f1);
                const int idx = (gd * 8 + dd) * 64 + egrp * 8 + ee * 2;
                reg0[idx]     = f0;
                reg0[idx + 1] = f1;
            }
        }
    }
    __syncthreads();
    float* dst = g_ctxp + ((size_t)bh * NSPLIT + split) * (DH * DH);
    for (int i = tid; i < DH * DH; i += 256)
        dst[i] = sm[i] + sm[4096 + i] + sm[8192 + i] + sm[12288 + i];
    __syncthreads();   // reads done before vsum reuses region 0

    // ---- vsum partial ----
    #pragma unroll
    for (int j = 0; j < 8; j++) sm[lrow * 64 + lcol8 * 8 + j] = vsum[j];
    __syncthreads();
    if (tid < DH) {
        float s = 0.f;
        #pragma unroll
        for (int r = 0; r < 32; r++) s += sm[r * 64 + tid];
        g_vsump[((size_t)bh * NSPLIT + split) * DH + tid] = s;
    }
}

// ===========================================================================
// K2: WARP-DECOUPLED: warp w owns rows w*16..w*16+15 of each 128-row tile
// end-to-end (EW -> GEMV -> tail). No block barriers in the loop — only
// __syncwarp(). v1 raw stride 70; ctx group-padded stride 96; 3 CTAs/SM.
// Half-angle mobius tail (exact, no libm).
// ===========================================================================
#define V1S 70
#define K2_CTX  0                 // 64*96 = 6144
#define K2_V1   6144              // 128*70 = 8960
#define K2_DP   15104             // 128
#define K2_VS   15232             // 64
#define K2_FLOATS 15296           // 61184 bytes

__global__ void __launch_bounds__(256, 3)
out_kernel(const float* __restrict__ Qg, const float* __restrict__ c,
           int csize, int N, int splits, float* __restrict__ out)
{
    extern __shared__ float sm[];
    float* ctx_s = sm + K2_CTX;
    float* v1s   = sm + K2_V1;
    float* dpbuf = sm + K2_DP;
    float* vs_s  = sm + K2_VS;

    const int chunk = blockIdx.x, bh = blockIdx.y;
    const int rows  = N / gridDim.x;
    const int n0    = chunk * rows;
    const float k   = (csize > 1) ? c[bh % csize] : c[0];
    const float sk  = sqrtf(fabsf(k) + 1e-15f);
    const float maxnorm = (k < 0.f) ? (1.f - 0.004f) / sk : 1e15f;
    const bool  hyp = (k < 0.f);

    const int tid   = threadIdx.x;
    const int wid   = tid >> 5, lane = tid & 31;
    const int lrow4 = lane >> 3, lcol8 = lane & 7;
    const int rgrp  = lane >> 3, egrp = lane & 7;
    const int e0    = egrp * 8;

    const float* Qp = Qg + (size_t)bh * N * DH;
    const float* rv = g_rinv + (size_t)bh * N;
    float*       Op = out + (size_t)bh * N * DH;

    // ---- fused reduce of K1 split partials (L2-hot) ----
    const float* bctx = g_ctxp + (size_t)bh * NSPLIT * DH * DH;
    for (int i = tid; i < DH * DH; i += 256) {
        float s = 0.f;
        for (int p = 0; p < splits; p++) s += bctx[p * DH * DH + i];
        const int d = i >> 6, e = i & 63;
        ctx_s[d * 96 + (e >> 3) * 12 + (e & 7)] = s;
    }
    if (tid < DH) {
        float s = 0.f;
        for (int p = 0; p < splits; p++) s += g_vsump[((size_t)bh * NSPLIT + p) * DH + tid];
        vs_s[tid] = s;
    }
    __syncthreads();   // ctx_s / vs_s read-only hereafter

    const int nIter = rows / 128;
    for (int it = 0; it < nIter; it++) {
        const int base = n0 + it * 128;

        // ---- EW: warp w computes v1 for ITS rows w*16..w*16+15 ----
        #pragma unroll
        for (int s = 0; s < 4; s++) {
            const int lr = wid * 16 + s * 4 + lrow4;
            const int n  = base + lr;
            const float rinv = rv[n];
            const size_t nb = (size_t)n * DH + lcol8 * 8;
            const float4 qa = *(const float4*)(Qp + nb);
            const float4 qb = *(const float4*)(Qp + nb + 4);
            float v1v[8];
            v1v[0] = elu1(qa.x*rinv); v1v[1] = elu1(qa.y*rinv);
            v1v[2] = elu1(qa.z*rinv); v1v[3] = elu1(qa.w*rinv);
            v1v[4] = elu1(qb.x*rinv); v1v[5] = elu1(qb.y*rinv);
            v1v[6] = elu1(qb.z*rinv); v1v[7] = elu1(qb.w*rinv);

            const int vc = lcol8 * 8;
            float dp = v1v[0]*vs_s[vc+0] + v1v[1]*vs_s[vc+1]
                     + v1v[2]*vs_s[vc+2] + v1v[3]*vs_s[vc+3]
                     + v1v[4]*vs_s[vc+4] + v1v[5]*vs_s[vc+5]
                     + v1v[6]*vs_s[vc+6] + v1v[7]*vs_s[vc+7];
            dp += __shfl_xor_sync(0xffffffffu, dp, 1);
            dp += __shfl_xor_sync(0xffffffffu, dp, 2);
            dp += __shfl_xor_sync(0xffffffffu, dp, 4);

            float* vw = &v1s[lr * V1S + vc];
            *(float2*)(vw)     = make_float2(v1v[0], v1v[1]);
            *(float2*)(vw + 2) = make_float2(v1v[2], v1v[3]);
            *(float2*)(vw + 4) = make_float2(v1v[4], v1v[5]);
            *(float2*)(vw + 6) = make_float2(v1v[6], v1v[7]);
            if (lcol8 == 0) dpbuf[lr] = dp;
        }
        __syncwarp();   // warp's v1/dp visible to warp's GEMV

        // ---- GEMV: thread = 4 of the warp's rows x 8 e ----
        const int row0 = wid * 16 + rgrp * 4;
        u64t acc[4][4] = {};
        #pragma unroll
        for (int d = 0; d < DH; d += 2) {
            const ulonglong2* bp0 = (const ulonglong2*)&ctx_s[d * 96 + egrp * 12];
            const ulonglong2* bp1 = (const ulonglong2*)&ctx_s[(d + 1) * 96 + egrp * 12];
            const ulonglong2 bA = bp0[0], bB = bp0[1];
            const ulonglong2 cA = bp1[0], cB = bp1[1];
            #pragma unroll
            for (int rr = 0; rr < 4; rr++) {
                const u64t ar = *(const u64t*)&v1s[(row0 + rr) * V1S + d];
                float a0, a1; upk2(ar, a0, a1);
                const u64t aa0 = pk2(a0, a0), aa1 = pk2(a1, a1);
                fma2(acc[rr][0], aa0, bA.x); fma2(acc[rr][1], aa0, bA.y);
                fma2(acc[rr][2], aa0, bB.x); fma2(acc[rr][3], aa0, bB.y);
                fma2(acc[rr][0], aa1, cA.x); fma2(acc[rr][1], aa1, cA.y);
                fma2(acc[rr][2], aa1, cB.x); fma2(acc[rr][3], aa1, cB.y);
            }
        }

        // ---- tail: Dinv scale, project -> mobius(0.5) -> project, store ----
        #pragma unroll
        for (int rr = 0; rr < 4; rr++) {
            const int lr = row0 + rr;
            const int n  = base + lr;
            float x[8];
            upk2(acc[rr][0], x[0], x[1]); upk2(acc[rr][1], x[2], x[3]);
            upk2(acc[rr][2], x[4], x[5]); upk2(acc[rr][3], x[6], x[7]);

            const float dp = dpbuf[lr];
            const float Dinv = 1.f / ((dp == 0.f) ? 1e-5f : dp);
            float n2 = 0.f;
            #pragma unroll
            for (int j = 0; j < 8; j++) { x[j] *= Dinv; n2 += x[j] * x[j]; }
            n2 += __shfl_xor_sync(0xffffffffu, n2, 1);
            n2 += __shfl_xor_sync(0xffffffffu, n2, 2);
            n2 += __shfl_xor_sync(0xffffffffu, n2, 4);

            const float norm = fmaxf(sqrtf(n2), 1e-15f);
            const float scl  = (norm > maxnorm) ? (maxnorm / norm) : 1.f;
            const float xn   = fmaxf(norm * scl, 1e-15f);
            // mobius scalar mul r=0.5 via half-angle identities (exact):
            //   k<0: tanh(atanh(y)/2) = y / (1 + sqrt(1 - y^2))
            //   k>0: tan(atan(z)/2)   = z / (1 + sqrt(1 + z^2))
            float tk;
            if (hyp) {
                const float y = fminf(sk * xn, 1.f - 1e-7f);
                tk = y / ((1.f + sqrtf(fmaxf(1.f - y * y, 0.f))) * sk);
            } else {
                const float z = sk * xn;
                tk = z / ((1.f + sqrtf(1.f + z * z)) * sk);
            }
            const float s2   = tk / xn;
            const float nrm2 = fmaxf(fabsf(tk), 1e-15f);
            const float scl2 = (nrm2 > maxnorm) ? (maxnorm / nrm2) : 1.f;
            const float st   = scl * s2 * scl2;

            float* o = Op + (size_t)n * DH + e0;
            *(float4*)(o)     = make_float4(x[0]*st, x[1]*st, x[2]*st, x[3]*st);
            *(float4*)(o + 4) = make_float4(x[4]*st, x[5]*st, x[6]*st, x[7]*st);
        }
        __syncwarp();   // warp's GEMV/tail reads done before its next EW writes
    }
}

extern "C" void kernel_launch(void* const* d_in, const int* in_sizes, int n_in,
                              void* d_out, int out_size)
{
    const float* Q    = (const float*)d_in[0];
    const float* K    = (const float*)d_in[1];
    const float* V    = (const float*)d_in[2];
    const float* mask = (const float*)d_in[3];
    const float* c    = (const float*)d_in[4];
    const int csize = in_sizes[4];
    const int N     = in_sizes[3];
    const int BH    = in_sizes[0] / (N * DH);

    int splits = NSPLIT;
    while (splits > 1 && (N % (splits * 32) != 0)) splits >>= 1;
    int chunks = NSPLIT;
    while (chunks > 1 && (N % (chunks * 128) != 0)) chunks >>= 1;

    cudaFuncSetAttribute(ctx_kernel, cudaFuncAttributeMaxDynamicSharedMemorySize,
                         K1_FLOATS * sizeof(float));
    cudaFuncSetAttribute(out_kernel, cudaFuncAttributeMaxDynamicSharedMemorySize,
                         K2_FLOATS * sizeof(float));

    dim3 g1(splits, BH);
    ctx_kernel<<<g1, 256, K1_FLOATS * sizeof(float)>>>(K, V, mask, c, csize, N);
    dim3 g2(chunks, BH);
    out_kernel<<<g2, 256, K2_FLOATS * sizeof(float)>>>(Q, c, csize, N, splits, (float*)d_out);
}